// round 1
// baseline (speedup 1.0000x reference)
#include <cuda_runtime.h>

// Problem constants (fixed shapes from reference: [16, 2, 768, 768], NUM_IT=4)
#define Nn   16
#define Hh   768
#define Ww   768
#define HW   (Hh * Ww)        // 589824
#define NHW  (Nn * HW)        // 9437184

// Ping-pong scratch in interleaved float2 layout [N, H, W] (75.5 MB each).
// __device__ globals — no runtime allocation (allocation guards).
__device__ static float2 g_bufA[NHW];
__device__ static float2 g_bufB[NHW];

__device__ __forceinline__ int clamp0(int v, int hi) {
    return v < 0 ? 0 : (v > hi ? hi : v);
}

// Iteration 0: read planar input [N,2,H,W], gather planar, write interleaved float2.
__global__ __launch_bounds__(256) void iter_first(const float* __restrict__ in,
                                                  float2* __restrict__ out) {
    int idx = blockIdx.x * blockDim.x + threadIdx.x;
    if (idx >= NHW) return;
    int n   = idx / HW;
    int rem = idx - n * HW;
    int y   = rem / Ww;
    int x   = rem - y * Ww;

    const float* base = in + (size_t)n * (2 * HW);
    float dx = __ldg(base + rem);
    float dy = __ldg(base + HW + rem);

    // trunc-toward-zero cast matches JAX astype(int32) / torch .long()
    int cx = clamp0((int)((float)x + dx), Ww - 1);
    int cy = clamp0((int)((float)y + dy), Hh - 1);
    int gi = cy * Ww + cx;

    float gx = __ldg(base + gi);
    float gy = __ldg(base + HW + gi);
    out[idx] = make_float2(dx + gx, dy + gy);
}

// Iterations 1,2: float2 -> float2, single 8B gather per pixel.
__global__ __launch_bounds__(256) void iter_mid(const float2* __restrict__ in,
                                                float2* __restrict__ out) {
    int idx = blockIdx.x * blockDim.x + threadIdx.x;
    if (idx >= NHW) return;
    int n   = idx / HW;
    int rem = idx - n * HW;
    int y   = rem / Ww;
    int x   = rem - y * Ww;

    float2 d = in[idx];
    int cx = clamp0((int)((float)x + d.x), Ww - 1);
    int cy = clamp0((int)((float)y + d.y), Hh - 1);
    float2 g = __ldg(&in[n * HW + cy * Ww + cx]);
    out[idx] = make_float2(d.x + g.x, d.y + g.y);
}

// Iteration 3 (last): produce all three outputs.
//   out_disp  : planar [N,2,H,W] f32
//   num_touch : [N,H,W]   as f32 via atomicAdd (exact for counts < 2^24)
//   pred_cent : [N,3,H,W] as f32 = (n, cx, cy)
__global__ __launch_bounds__(256) void iter_last(const float2* __restrict__ in,
                                                 float* __restrict__ out_disp,
                                                 float* __restrict__ num_touch,
                                                 float* __restrict__ pred_cent) {
    int idx = blockIdx.x * blockDim.x + threadIdx.x;
    if (idx >= NHW) return;
    int n   = idx / HW;
    int rem = idx - n * HW;
    int y   = rem / Ww;
    int x   = rem - y * Ww;

    float2 d = in[idx];
    int cx = clamp0((int)((float)x + d.x), Ww - 1);
    int cy = clamp0((int)((float)y + d.y), Hh - 1);
    float2 g = __ldg(&in[n * HW + cy * Ww + cx]);

    size_t db = (size_t)n * (2 * HW) + rem;
    out_disp[db]      = d.x + g.x;
    out_disp[db + HW] = d.y + g.y;

    atomicAdd(&num_touch[n * HW + cy * Ww + cx], 1.0f);

    size_t pb = (size_t)n * (3 * HW) + rem;
    pred_cent[pb]            = (float)n;
    pred_cent[pb + HW]       = (float)cx;
    pred_cent[pb + 2 * HW]   = (float)cy;
}

extern "C" void kernel_launch(void* const* d_in, const int* in_sizes, int n_in,
                              void* d_out, int out_size) {
    (void)in_sizes; (void)n_in; (void)out_size;
    const float* pred_disp = (const float*)d_in[0];
    float* out = (float*)d_out;

    // Output layout: disp [N*2*H*W] | num_touch [N*H*W] | pred_cent [N*3*H*W]
    float* out_disp  = out;
    float* out_touch = out + (size_t)2 * NHW;   // 2*NHW = N*2*H*W elems of disp
    float* out_cent  = out_touch + NHW;

    float2 *bufA = nullptr, *bufB = nullptr;
    cudaGetSymbolAddress((void**)&bufA, g_bufA);
    cudaGetSymbolAddress((void**)&bufB, g_bufB);

    const int threads = 256;
    const int blocks  = (NHW + threads - 1) / threads;  // 36864

    // num_touch must start from zeros (d_out is poisoned before timing)
    cudaMemsetAsync(out_touch, 0, (size_t)NHW * sizeof(float));

    iter_first<<<blocks, threads>>>(pred_disp, bufA);          // it 0: input -> A
    iter_mid  <<<blocks, threads>>>(bufA, bufB);               // it 1: A -> B
    iter_mid  <<<blocks, threads>>>(bufB, bufA);               // it 2: B -> A
    iter_last <<<blocks, threads>>>(bufA, out_disp, out_touch, out_cent); // it 3
}

// round 2
// speedup vs baseline: 1.0275x; 1.0275x over previous
#include <cuda_runtime.h>

// Fixed shapes from reference: [16, 2, 768, 768], NUM_IT=4
#define Nn   16
#define Hh   768
#define Ww   768
#define HW   (Hh * Ww)        // 589824
#define NHW  (Nn * HW)        // 9437184
#define NPIX2 (NHW / 2)       // 2 pixels per thread

// Ping-pong scratch, interleaved float2 [N,H,W] (75.5 MB each).
__device__ static float2 g_bufA[NHW];
__device__ static float2 g_bufB[NHW];

__device__ __forceinline__ int clamp0(int v, int hi) {
    return v < 0 ? 0 : (v > hi ? hi : v);
}

// Streaming (evict-first) stores: keep gather source resident in L2.
__device__ __forceinline__ void stcs2(float2* p, float2 v) {
    __stcs(p, v);
}
__device__ __forceinline__ void stcs4(float4* p, float4 v) {
    __stcs(p, v);
}

// Iteration 0: planar input [N,2,H,W] -> interleaved float2. 2 px/thread.
__global__ __launch_bounds__(256) void iter_first(const float* __restrict__ in,
                                                  float2* __restrict__ out) {
    int t = blockIdx.x * blockDim.x + threadIdx.x;
    if (t >= NPIX2) return;
    int idx = t * 2;
    int n   = idx / HW;
    int rem = idx - n * HW;
    int y   = rem / Ww;
    int x   = rem - y * Ww;          // x even, x+1 < Ww (Ww even)

    const float* base = in + (size_t)n * (2 * HW);
    float2 dx2 = *(const float2*)(base + rem);        // dx for px0,px1
    float2 dy2 = *(const float2*)(base + HW + rem);   // dy for px0,px1

    int cx0 = clamp0((int)((float)x + dx2.x),     Ww - 1);
    int cy0 = clamp0((int)((float)y + dy2.x),     Hh - 1);
    int cx1 = clamp0((int)((float)(x+1) + dx2.y), Ww - 1);
    int cy1 = clamp0((int)((float)y + dy2.y),     Hh - 1);
    int gi0 = cy0 * Ww + cx0;
    int gi1 = cy1 * Ww + cx1;

    // 4 independent scattered loads -> MLP
    float gx0 = __ldg(base + gi0);
    float gx1 = __ldg(base + gi1);
    float gy0 = __ldg(base + HW + gi0);
    float gy1 = __ldg(base + HW + gi1);

    float4 o = make_float4(dx2.x + gx0, dy2.x + gy0, dx2.y + gx1, dy2.y + gy1);
    stcs4((float4*)&out[idx], o);
}

// Iterations 1,2: float2 -> float2, 2 px/thread, 2 independent 8B gathers.
// ZERO_TOUCH!=0: also zero the num_touch region (folds in the memset).
template <int ZERO_TOUCH>
__global__ __launch_bounds__(256) void iter_mid(const float2* __restrict__ in,
                                                float2* __restrict__ out,
                                                float* __restrict__ touch) {
    int t = blockIdx.x * blockDim.x + threadIdx.x;
    if (t >= NPIX2) return;
    int idx = t * 2;
    int n   = idx / HW;
    int rem = idx - n * HW;
    int y   = rem / Ww;
    int x   = rem - y * Ww;

    float4 d = *(const float4*)&in[idx];   // (dx0,dy0,dx1,dy1)

    int cx0 = clamp0((int)((float)x + d.x),     Ww - 1);
    int cy0 = clamp0((int)((float)y + d.y),     Hh - 1);
    int cx1 = clamp0((int)((float)(x+1) + d.z), Ww - 1);
    int cy1 = clamp0((int)((float)y + d.w),     Hh - 1);

    const float2* plane = in + n * HW;
    float2 g0 = __ldg(&plane[cy0 * Ww + cx0]);
    float2 g1 = __ldg(&plane[cy1 * Ww + cx1]);

    float4 o = make_float4(d.x + g0.x, d.y + g0.y, d.z + g1.x, d.w + g1.y);
    stcs4((float4*)&out[idx], o);

    if (ZERO_TOUCH) {
        stcs2((float2*)&touch[idx], make_float2(0.0f, 0.0f));
    }
}

// Iteration 3 (last): write disp (planar), num_touch (atomic f32), pred_cent.
__global__ __launch_bounds__(256) void iter_last(const float2* __restrict__ in,
                                                 float* __restrict__ out_disp,
                                                 float* __restrict__ num_touch,
                                                 float* __restrict__ pred_cent) {
    int t = blockIdx.x * blockDim.x + threadIdx.x;
    if (t >= NPIX2) return;
    int idx = t * 2;
    int n   = idx / HW;
    int rem = idx - n * HW;
    int y   = rem / Ww;
    int x   = rem - y * Ww;

    float4 d = *(const float4*)&in[idx];

    int cx0 = clamp0((int)((float)x + d.x),     Ww - 1);
    int cy0 = clamp0((int)((float)y + d.y),     Hh - 1);
    int cx1 = clamp0((int)((float)(x+1) + d.z), Ww - 1);
    int cy1 = clamp0((int)((float)y + d.w),     Hh - 1);

    const float2* plane = in + n * HW;
    float2 g0 = __ldg(&plane[cy0 * Ww + cx0]);
    float2 g1 = __ldg(&plane[cy1 * Ww + cx1]);

    // disp planar [N,2,H,W]
    size_t db = (size_t)n * (2 * HW) + rem;
    stcs2((float2*)&out_disp[db],      make_float2(d.x + g0.x, d.z + g1.x));
    stcs2((float2*)&out_disp[db + HW], make_float2(d.y + g0.y, d.w + g1.y));

    // touch counts (float adds are exact for small counts)
    float* tplane = num_touch + n * HW;
    atomicAdd(&tplane[cy0 * Ww + cx0], 1.0f);
    atomicAdd(&tplane[cy1 * Ww + cx1], 1.0f);

    // pred_cent [N,3,H,W] = (n, cx, cy)
    size_t pb = (size_t)n * (3 * HW) + rem;
    float fn = (float)n;
    stcs2((float2*)&pred_cent[pb],          make_float2(fn, fn));
    stcs2((float2*)&pred_cent[pb + HW],     make_float2((float)cx0, (float)cx1));
    stcs2((float2*)&pred_cent[pb + 2 * HW], make_float2((float)cy0, (float)cy1));
}

extern "C" void kernel_launch(void* const* d_in, const int* in_sizes, int n_in,
                              void* d_out, int out_size) {
    (void)in_sizes; (void)n_in; (void)out_size;
    const float* pred_disp = (const float*)d_in[0];
    float* out = (float*)d_out;

    // Output layout: disp [N*2*H*W] | num_touch [N*H*W] | pred_cent [N*3*H*W]
    float* out_disp  = out;
    float* out_touch = out + (size_t)2 * NHW;
    float* out_cent  = out_touch + NHW;

    float2 *bufA = nullptr, *bufB = nullptr;
    cudaGetSymbolAddress((void**)&bufA, g_bufA);
    cudaGetSymbolAddress((void**)&bufB, g_bufB);

    const int threads = 256;
    const int blocks  = (NPIX2 + threads - 1) / threads;   // 18432

    iter_first<<<blocks, threads>>>(pred_disp, bufA);                 // it 0
    iter_mid<0><<<blocks, threads>>>(bufA, bufB, nullptr);            // it 1
    iter_mid<1><<<blocks, threads>>>(bufB, bufA, out_touch);          // it 2 + zero touch
    iter_last<<<blocks, threads>>>(bufA, out_disp, out_touch, out_cent); // it 3
}